// round 3
// baseline (speedup 1.0000x reference)
#include <cuda_runtime.h>
#include <cuda_bf16.h>

#define BS 128
#define GS 201
#define DIM 128
#define HALF 100
#define GS2 (GS*GS)
#define OUTS (HALF + GS2)
#define NORMF 0.08838834764831845f
#define NTILES 26

// ---- device scratch ----
__device__ float g_gmax[BS*DIM];
__device__ float g_gb[BS*DIM];
__device__ float g_h[BS*GS*DIM];
__device__ float g_hQ[BS*GS*DIM];
__device__ float g_hK[BS*GS*DIM];
__device__ float g_qW[BS*4*4*DIM];
__device__ float g_u[BS*GS*32];
__device__ float g_v[BS*GS*32];
__device__ float g_part[BS*NTILES];
__device__ float g_sums[BS];

// ---- f32x2 helpers ----
__device__ __forceinline__ unsigned long long pack2(float lo, float hi){
    unsigned long long r; asm("mov.b64 %0, {%1, %2};" : "=l"(r) : "f"(lo), "f"(hi)); return r;
}
__device__ __forceinline__ float2 unpack2(unsigned long long v){
    float2 r; asm("mov.b64 {%0, %1}, %2;" : "=f"(r.x), "=f"(r.y) : "l"(v)); return r;
}
__device__ __forceinline__ unsigned long long fma2(unsigned long long a, unsigned long long b, unsigned long long c){
    unsigned long long r; asm("fma.rn.f32x2 %0, %1, %2, %3;" : "=l"(r) : "l"(a), "l"(b), "l"(c)); return r;
}
__device__ __forceinline__ float fast_tanh(float y){
    y = fminf(fmaxf(y, -15.f), 15.f);
    float e = __expf(2.f*y);
    return __fdividef(e-1.f, e+1.f);
}

// ---- max over nodes ----
__global__ void k_gmax(const float* __restrict__ h_em){
    int b = blockIdx.x, d = threadIdx.x;
    const float* p = h_em + (size_t)b*GS*DIM + d;
    float m = -1e30f;
    for (int g = 0; g < GS; ++g) m = fmaxf(m, p[(size_t)g*DIM]);
    g_gmax[b*DIM+d] = m;
}

// ---- gb = gmax @ Wg ----
__global__ void k_gb(const float* __restrict__ Wg){
    __shared__ float xs[DIM];
    int b = blockIdx.x, c = threadIdx.x;
    xs[c] = g_gmax[b*DIM+c];
    __syncthreads();
    float acc = 0.f;
    #pragma unroll 8
    for (int i = 0; i < DIM; ++i) acc = fmaf(xs[i], Wg[i*DIM+c], acc);
    g_gb[b*DIM+c] = acc;
}

// ---- GEMM (25728x128)@(128x128). MODE0: h = h_em@Wn + gb; MODE1: hQ; MODE2: hK ----
template<int MODE>
__global__ __launch_bounds__(256) void k_gemm(const float* __restrict__ Aext, const float* __restrict__ B){
    __shared__ float As[64][17];
    __shared__ float Bs[16][128];
    const float* A = (MODE == 0) ? Aext : g_h;
    float* C = (MODE == 0) ? g_h : ((MODE == 1) ? g_hQ : g_hK);
    int tid = threadIdx.x;
    int tx = tid & 15, ty = tid >> 4;
    int row0 = blockIdx.x * 64;
    float acc[4][8];
    #pragma unroll
    for (int a = 0; a < 4; ++a)
        #pragma unroll
        for (int c = 0; c < 8; ++c) acc[a][c] = 0.f;
    int la_r = tid >> 2, la_k = (tid & 3)*4;
    int lb_r = tid >> 4, lb_c = (tid & 15)*8;
    for (int kc = 0; kc < DIM; kc += 16){
        float4 av = *reinterpret_cast<const float4*>(A + (size_t)(row0+la_r)*DIM + kc + la_k);
        const float* bp;
        if (MODE == 0) bp = B + (kc+lb_r)*DIM + lb_c;
        else           bp = B + (lb_c>>5)*4096 + (kc+lb_r)*32 + (lb_c&31);
        float4 bv0 = *reinterpret_cast<const float4*>(bp);
        float4 bv1 = *reinterpret_cast<const float4*>(bp+4);
        As[la_r][la_k+0]=av.x; As[la_r][la_k+1]=av.y; As[la_r][la_k+2]=av.z; As[la_r][la_k+3]=av.w;
        *reinterpret_cast<float4*>(&Bs[lb_r][lb_c])   = bv0;
        *reinterpret_cast<float4*>(&Bs[lb_r][lb_c+4]) = bv1;
        __syncthreads();
        #pragma unroll
        for (int k = 0; k < 16; ++k){
            float a0=As[ty*4+0][k], a1=As[ty*4+1][k], a2=As[ty*4+2][k], a3=As[ty*4+3][k];
            float4 b0 = *reinterpret_cast<const float4*>(&Bs[k][tx*8]);
            float4 b1 = *reinterpret_cast<const float4*>(&Bs[k][tx*8+4]);
            float bb[8] = {b0.x,b0.y,b0.z,b0.w,b1.x,b1.y,b1.z,b1.w};
            #pragma unroll
            for (int c = 0; c < 8; ++c){
                acc[0][c]=fmaf(a0,bb[c],acc[0][c]); acc[1][c]=fmaf(a1,bb[c],acc[1][c]);
                acc[2][c]=fmaf(a2,bb[c],acc[2][c]); acc[3][c]=fmaf(a3,bb[c],acc[3][c]);
            }
        }
        __syncthreads();
    }
    #pragma unroll
    for (int a = 0; a < 4; ++a){
        int row = row0 + ty*4 + a;
        #pragma unroll
        for (int c = 0; c < 8; ++c){
            float v = acc[a][c];
            if (MODE == 0) v += g_gb[(row/GS)*DIM + tx*8 + c];
            C[(size_t)row*DIM + tx*8 + c] = v;
        }
    }
}

// ---- 16 effective query vectors: qW = Wk (Wq^T h_sel) ----
__global__ void k_qW(const float* __restrict__ Wq1, const float* __restrict__ Wk1,
                     const float* __restrict__ Wq2, const float* __restrict__ Wk2,
                     const int* __restrict__ fixed_action){
    int b = blockIdx.x, combo = blockIdx.y, t = threadIdx.x;
    __shared__ float xs[DIM], tmp[DIM];
    int pos = 1 + fixed_action[b*3];
    int sel = (combo & 2) ? pos + HALF : pos;
    const float* Wq = (combo & 1) ? Wq2 : Wq1;
    const float* Wk = (combo & 1) ? Wk2 : Wk1;
    xs[t] = g_h[((size_t)b*GS + sel)*DIM + t];
    __syncthreads();
    for (int hh = 0; hh < 4; ++hh){
        const float* wq = Wq + hh*DIM*DIM;
        float acc = 0.f;
        #pragma unroll 8
        for (int i = 0; i < DIM; ++i) acc = fmaf(xs[i], wq[i*DIM+t], acc);
        __syncthreads();
        tmp[t] = acc;
        __syncthreads();
        const float* wk = Wk + hh*DIM*DIM + t*DIM;
        float o = 0.f;
        #pragma unroll 8
        for (int k = 0; k < DIM; ++k) o = fmaf(tmp[k], wk[k], o);
        g_qW[((b*4+combo)*4+hh)*DIM + t] = o;
    }
}

// ---- per-node layer-1 pre-activations ----
__global__ void k_uv(const int* __restrict__ rec, const float* __restrict__ i_w1,
                     const float* __restrict__ i_b1){
    int g = blockIdx.x, b = blockIdx.y, t = threadIdx.x;
    __shared__ float xg[DIM], xn[DIM], s[16];
    int rg = rec[b*GS + g];
    xg[t] = g_h[((size_t)b*GS + g )*DIM + t];
    xn[t] = g_h[((size_t)b*GS + rg)*DIM + t];
    __syncthreads();
    int d = t >> 3, l8 = t & 7;
    int combo = d >> 2, head = d & 3;
    const float* q = g_qW + ((b*4+combo)*4+head)*DIM;
    const float* x = (combo & 1) ? xn : xg;
    float p = 0.f;
    #pragma unroll
    for (int e = l8; e < DIM; e += 8) p = fmaf(q[e], x[e], p);
    p += __shfl_xor_sync(0xffffffffu, p, 4);
    p += __shfl_xor_sync(0xffffffffu, p, 2);
    p += __shfl_xor_sync(0xffffffffu, p, 1);
    if (l8 == 0) s[d] = p * NORMF;
    __syncthreads();
    if (t < 32){
        float u = i_b1[t];
        #pragma unroll
        for (int f = 0; f < 8; ++f) u = fmaf(s[f], i_w1[f*32+t], u);
        g_u[((size_t)b*GS + g)*32 + t] = u;
    } else if (t < 64){
        int c = t - 32;
        float v = 0.f;
        #pragma unroll
        for (int f = 0; f < 8; ++f) v = fmaf(s[8+f], i_w1[(8+f)*32+c], v);
        g_v[((size_t)b*GS + g)*32 + c] = v;
    }
}

// ---- removal scores ----
__global__ void k_removal(const int* __restrict__ rec, const float* __restrict__ sig,
                          const float* __restrict__ w1, const float* __restrict__ b1,
                          const float* __restrict__ w2, const float* __restrict__ b2,
                          const float* __restrict__ w3, const float* __restrict__ b3,
                          float* __restrict__ out){
    int b = blockIdx.x, t = threadIdx.x;
    __shared__ int rec_s[GS], pre_s[GS];
    __shared__ float red[4];
    __shared__ float tot_s;
    for (int g = t; g < GS; g += 128) rec_s[g] = rec[b*GS+g];
    __syncthreads();
    for (int g = t; g < GS; g += 128) pre_s[rec_s[g]] = g;
    __syncthreads();
    float e = 0.f;
    if (t < HALF){
        float feat[12];
        #pragma unroll
        for (int hf = 0; hf < 2; ++hf){
            int g = 1 + hf*HALF + t;
            int pg = pre_s[g];
            int og = rec_s[rec_s[g]];
            const float* Qg = g_hQ + ((size_t)b*GS + g )*DIM;
            const float* Kg = g_hK + ((size_t)b*GS + g )*DIM;
            const float* Qp = g_hQ + ((size_t)b*GS + pg)*DIM;
            const float* Kp = g_hK + ((size_t)b*GS + og)*DIM;
            #pragma unroll
            for (int h = 0; h < 4; ++h){
                float c1=0.f, c2=0.f, c3=0.f;
                #pragma unroll
                for (int k = 0; k < 32; ++k){
                    float qp=Qp[h*32+k], kg=Kg[h*32+k], qg=Qg[h*32+k], kp=Kp[h*32+k];
                    c1 = fmaf(qp, kg, c1);
                    c2 = fmaf(qg, kp, c2);
                    c3 = fmaf(qp, kp, c3);
                }
                feat[hf*4+h] = c1 + c2 - c3;
            }
        }
        #pragma unroll
        for (int s4 = 0; s4 < 4; ++s4) feat[8+s4] = sig[b*4*HALF + s4*HALF + t];
        float x1[32];
        #pragma unroll
        for (int c = 0; c < 32; ++c){
            float a = b1[c];
            #pragma unroll
            for (int f = 0; f < 12; ++f) a = fmaf(feat[f], w1[f*32+c], a);
            x1[c] = fmaxf(a, 0.f);
        }
        float y = b3[0];
        #pragma unroll
        for (int o = 0; o < 32; ++o){
            float a = b2[o];
            #pragma unroll
            for (int k = 0; k < 32; ++k) a = fmaf(x1[k], w2[k*32+o], a);
            y = fmaf(fmaxf(a, 0.f), w3[o], y);
        }
        e = __expf(6.f * tanhf(y));
    }
    float w = e;
    #pragma unroll
    for (int o = 16; o; o >>= 1) w += __shfl_xor_sync(0xffffffffu, w, o);
    if ((t & 31) == 0) red[t>>5] = w;
    __syncthreads();
    if (t == 0) tot_s = red[0]+red[1]+red[2]+red[3];
    __syncthreads();
    if (t < HALF) out[(size_t)b*OUTS + t] = e / tot_s;
}

// ---- table MLP v2: stream-k, 32 packed accumulators, no big live array ----
// block: 256 thr = 8 warps; warp il handles row i = it*8+il, lanes cover j pairs.
__global__ __launch_bounds__(256, 2) void k_table(
        const float* __restrict__ i_w2, const float* __restrict__ i_b2,
        const float* __restrict__ i_w3, const float* __restrict__ i_b3,
        const unsigned char* __restrict__ mask, float* __restrict__ out){
    __shared__ unsigned long long w2k[32][32];   // dup weights, [k][o] layout
    __shared__ float2 vp[32][101];               // (v[2jp][k], v[2jp+1][k])
    __shared__ float us[8][32];
    __shared__ unsigned long long b2d[32];
    __shared__ float w3s[32];
    __shared__ float red[8];
    int tid = threadIdx.x, b = blockIdx.y, it = blockIdx.x;
    int lane = tid & 31, il = tid >> 5;

    for (int idx = tid; idx < 1024; idx += 256){
        int k = idx >> 5, o = idx & 31;
        float w = i_w2[k*32+o];
        w2k[k][o] = pack2(w, w);
    }
    if (tid < 32){
        float bb = i_b2[tid];
        b2d[tid] = pack2(bb, bb);
        w3s[tid] = i_w3[tid];
    }
    const float* vbase = g_v + (size_t)b*GS*32;
    for (int idx = tid; idx < 32*101; idx += 256){
        int k = idx / 101, jp = idx - 101*(idx/101);
        int j0 = 2*jp, j1 = min(2*jp+1, GS-1);
        vp[k][jp] = make_float2(vbase[(size_t)j0*32 + k], vbase[(size_t)j1*32 + k]);
    }
    {
        int i = it*8 + (tid >> 5);
        us[tid>>5][lane] = (i < GS) ? g_u[((size_t)b*GS + i)*32 + lane] : 0.f;
    }
    __syncthreads();

    int i = it*8 + il;
    bool iok = (i < GS);
    float b3v = i_b3[0];
    float lsum = 0.f;
    const unsigned char* mrow = mask + ((size_t)b*GS + i)*GS;
    float* orow = out + (size_t)b*OUTS + HALF + (size_t)i*GS;

    #pragma unroll 1
    for (int p = 0; p < 4; ++p){
        int jp = p*32 + lane;            // pair index; j0=2jp, j1=2jp+1
        int jpc = min(jp, 100);
        unsigned long long acc[32];
        #pragma unroll
        for (int o = 0; o < 32; ++o) acc[o] = b2d[o];
        #pragma unroll 8
        for (int k = 0; k < 32; ++k){
            float2 v2 = vp[k][jpc];
            float uk = us[il][k];
            unsigned long long h = pack2(fmaxf(uk + v2.x, 0.f), fmaxf(uk + v2.y, 0.f));
            #pragma unroll
            for (int o = 0; o < 32; ++o)
                acc[o] = fma2(h, w2k[k][o], acc[o]);
        }
        float y0 = b3v, y1 = b3v;
        #pragma unroll
        for (int o = 0; o < 32; ++o){
            float2 r = unpack2(acc[o]);
            y0 = fmaf(fmaxf(r.x, 0.f), w3s[o], y0);
            y1 = fmaf(fmaxf(r.y, 0.f), w3s[o], y1);
        }
        int j0 = 2*jp, j1 = j0 + 1;
        if (iok && j0 < GS){
            float e = mrow[j0] ? 0.f : __expf(6.f * fast_tanh(y0));
            orow[j0] = e; lsum += e;
            if (j1 < GS){
                float e1 = mrow[j1] ? 0.f : __expf(6.f * fast_tanh(y1));
                orow[j1] = e1; lsum += e1;
            }
        }
    }
    #pragma unroll
    for (int o = 16; o; o >>= 1) lsum += __shfl_xor_sync(0xffffffffu, lsum, o);
    if (lane == 0) red[il] = lsum;
    __syncthreads();
    if (tid == 0){
        float tot = 0.f;
        #pragma unroll
        for (int w = 0; w < 8; ++w) tot += red[w];
        g_part[b*NTILES + it] = tot;
    }
}

// ---- deterministic row sums -> reciprocal ----
__global__ void k_inv(){
    int b = blockIdx.x, t = threadIdx.x;
    float v = (t < NTILES) ? g_part[b*NTILES + t] : 0.f;
    #pragma unroll
    for (int o = 16; o; o >>= 1) v += __shfl_xor_sync(0xffffffffu, v, o);
    if (t == 0) g_sums[b] = __frcp_rn(v);
}

// ---- normalize reinsertion block ----
__global__ void k_scale(float* __restrict__ out){
    int idx = blockIdx.x*256 + threadIdx.x;
    if (idx >= BS*GS2) return;
    int b = idx / GS2;
    out[(size_t)b*OUTS + HALF + (idx - b*GS2)] *= g_sums[b];
}

extern "C" void kernel_launch(void* const* d_in, const int* in_sizes, int n_in,
                              void* d_out, int out_size) {
    const float* h_em  = (const float*)d_in[0];
    const float* sig   = (const float*)d_in[1];
    const float* Wn    = (const float*)d_in[2];
    const float* Wg    = (const float*)d_in[3];
    const float* WQr   = (const float*)d_in[4];
    const float* WKr   = (const float*)d_in[5];
    const float* r_w1  = (const float*)d_in[6];
    const float* r_b1  = (const float*)d_in[7];
    const float* r_w2  = (const float*)d_in[8];
    const float* r_b2  = (const float*)d_in[9];
    const float* r_w3  = (const float*)d_in[10];
    const float* r_b3  = (const float*)d_in[11];
    const float* Wq1   = (const float*)d_in[12];
    const float* Wk1   = (const float*)d_in[13];
    const float* Wq2   = (const float*)d_in[14];
    const float* Wk2   = (const float*)d_in[15];
    const float* i_w1  = (const float*)d_in[16];
    const float* i_b1  = (const float*)d_in[17];
    const float* i_w2  = (const float*)d_in[18];
    const float* i_b2  = (const float*)d_in[19];
    const float* i_w3  = (const float*)d_in[20];
    const float* i_b3  = (const float*)d_in[21];
    const int*   rec   = (const int*)d_in[22];
    const int*   fixed = (const int*)d_in[23];
    const unsigned char* mask = (const unsigned char*)d_in[24];
    float* out = (float*)d_out;

    // order chosen so k_table is launch #6 (ncu -s 5 -c 1 lands on it)
    k_gmax<<<BS, 128>>>(h_em);
    k_gb<<<BS, 128>>>(Wg);
    k_gemm<0><<<402, 256>>>(h_em, Wn);
    k_qW<<<dim3(BS, 4), 128>>>(Wq1, Wk1, Wq2, Wk2, fixed);
    k_uv<<<dim3(GS, BS), 128>>>(rec, i_w1, i_b1);
    k_table<<<dim3(NTILES, BS), 256>>>(i_w2, i_b2, i_w3, i_b3, mask, out);
    k_gemm<1><<<402, 256>>>(nullptr, WQr);
    k_gemm<2><<<402, 256>>>(nullptr, WKr);
    k_removal<<<BS, 128>>>(rec, sig, r_w1, r_b1, r_w2, r_b2, r_w3, r_b3, out);
    k_inv<<<BS, 32>>>();
    k_scale<<<(BS*GS2 + 255)/256, 256>>>(out);
}

// round 6
// speedup vs baseline: 1.1151x; 1.1151x over previous
#include <cuda_runtime.h>
#include <cuda_bf16.h>

#define BS 128
#define GS 201
#define DIM 128
#define HALF 100
#define GS2 (GS*GS)
#define OUTS (HALF + GS2)
#define NORMF 0.08838834764831845f
#define NTILES 26

// ---- device scratch ----
__device__ float g_gb[BS*DIM];
__device__ float g_h[BS*GS*DIM];
__device__ float g_hQ[BS*GS*DIM];
__device__ float g_hK[BS*GS*DIM];
__device__ float g_Mt[8*DIM*DIM];
__device__ float g_qW[BS*4*4*DIM];
__device__ float g_u[BS*GS*32];
__device__ float g_v[BS*GS*32];
__device__ float g_part[BS*NTILES];
__device__ float g_sums[BS];

// ---- f32x2 helpers ----
__device__ __forceinline__ unsigned long long pack2(float lo, float hi){
    unsigned long long r; asm("mov.b64 %0, {%1, %2};" : "=l"(r) : "f"(lo), "f"(hi)); return r;
}
__device__ __forceinline__ float2 unpack2(unsigned long long v){
    float2 r; asm("mov.b64 {%0, %1}, %2;" : "=f"(r.x), "=f"(r.y) : "l"(v)); return r;
}
__device__ __forceinline__ unsigned long long fma2(unsigned long long a, unsigned long long b, unsigned long long c){
    unsigned long long r; asm("fma.rn.f32x2 %0, %1, %2, %3;" : "=l"(r) : "l"(a), "l"(b), "l"(c)); return r;
}
__device__ __forceinline__ float fast_tanh(float y){
    y = fminf(fmaxf(y, -15.f), 15.f);
    float e = __expf(2.f*y);
    return __fdividef(e-1.f, e+1.f);
}

// ---- k_prep: Mt[mat][i][j] = sum_e Wq[mat][i][e] * Wk[mat][j][e]  (data-independent) ----
__global__ __launch_bounds__(256) void k_prep(const float* __restrict__ Wq1, const float* __restrict__ Wk1,
                                              const float* __restrict__ Wq2, const float* __restrict__ Wk2){
    __shared__ float Wqs[16][33];
    __shared__ float Wks[32][129];
    int mat = blockIdx.x, kt = blockIdx.y;
    int s = mat >> 2, h = mat & 3;
    const float* Wq = (s ? Wq2 : Wq1) + h*DIM*DIM;
    const float* Wk = (s ? Wk2 : Wk1) + h*DIM*DIM;
    int tid = threadIdx.x;
    int j = tid & 127, rr = tid >> 7;
    float acc[8];
    #pragma unroll
    for (int r = 0; r < 8; ++r) acc[r] = 0.f;
    for (int e0 = 0; e0 < DIM; e0 += 32){
        for (int idx = tid; idx < 16*32; idx += 256){
            int r = idx >> 5, e = idx & 31;
            Wqs[r][e] = Wq[(kt*16 + r)*DIM + e0 + e];
        }
        for (int idx = tid; idx < 128*32; idx += 256){
            int row = idx >> 5, e = idx & 31;
            Wks[e][row] = Wk[row*DIM + e0 + e];
        }
        __syncthreads();
        #pragma unroll 8
        for (int e = 0; e < 32; ++e){
            float wv = Wks[e][j];
            #pragma unroll
            for (int r = 0; r < 8; ++r)
                acc[r] = fmaf(Wqs[rr*8 + r][e], wv, acc[r]);
        }
        __syncthreads();
    }
    #pragma unroll
    for (int r = 0; r < 8; ++r)
        g_Mt[mat*DIM*DIM + (kt*16 + rr*8 + r)*DIM + j] = acc[r];
}

// ---- fused: gmax (max over nodes) + gb = gmax @ Wg ----
__global__ void k_gg(const float* __restrict__ h_em, const float* __restrict__ Wg){
    __shared__ float xs[DIM];
    int b = blockIdx.x, d = threadIdx.x;
    const float* p = h_em + (size_t)b*GS*DIM + d;
    float m = -1e30f;
    for (int g = 0; g < GS; ++g) m = fmaxf(m, p[(size_t)g*DIM]);
    xs[d] = m;
    __syncthreads();
    float acc = 0.f;
    #pragma unroll 8
    for (int i = 0; i < DIM; ++i) acc = fmaf(xs[i], Wg[i*DIM+d], acc);
    g_gb[b*DIM+d] = acc;
}

// ---- GEMM mode 0: h = h_em@Wn + gb ----
__global__ __launch_bounds__(256) void k_gemm0(const float* __restrict__ A, const float* __restrict__ B){
    __shared__ float As[64][17];
    __shared__ float Bs[16][128];
    int tid = threadIdx.x;
    int tx = tid & 15, ty = tid >> 4;
    int row0 = blockIdx.x * 64;
    float acc[4][8];
    #pragma unroll
    for (int a = 0; a < 4; ++a)
        #pragma unroll
        for (int c = 0; c < 8; ++c) acc[a][c] = 0.f;
    int la_r = tid >> 2, la_k = (tid & 3)*4;
    int lb_r = tid >> 4, lb_c = (tid & 15)*8;
    for (int kc = 0; kc < DIM; kc += 16){
        float4 av = *reinterpret_cast<const float4*>(A + (size_t)(row0+la_r)*DIM + kc + la_k);
        const float* bp = B + (kc+lb_r)*DIM + lb_c;
        float4 bv0 = *reinterpret_cast<const float4*>(bp);
        float4 bv1 = *reinterpret_cast<const float4*>(bp+4);
        As[la_r][la_k+0]=av.x; As[la_r][la_k+1]=av.y; As[la_r][la_k+2]=av.z; As[la_r][la_k+3]=av.w;
        *reinterpret_cast<float4*>(&Bs[lb_r][lb_c])   = bv0;
        *reinterpret_cast<float4*>(&Bs[lb_r][lb_c+4]) = bv1;
        __syncthreads();
        #pragma unroll
        for (int k = 0; k < 16; ++k){
            float a0=As[ty*4+0][k], a1=As[ty*4+1][k], a2=As[ty*4+2][k], a3=As[ty*4+3][k];
            float4 b0 = *reinterpret_cast<const float4*>(&Bs[k][tx*8]);
            float4 b1 = *reinterpret_cast<const float4*>(&Bs[k][tx*8+4]);
            float bb[8] = {b0.x,b0.y,b0.z,b0.w,b1.x,b1.y,b1.z,b1.w};
            #pragma unroll
            for (int c = 0; c < 8; ++c){
                acc[0][c]=fmaf(a0,bb[c],acc[0][c]); acc[1][c]=fmaf(a1,bb[c],acc[1][c]);
                acc[2][c]=fmaf(a2,bb[c],acc[2][c]); acc[3][c]=fmaf(a3,bb[c],acc[3][c]);
            }
        }
        __syncthreads();
    }
    #pragma unroll
    for (int a = 0; a < 4; ++a){
        int row = row0 + ty*4 + a;
        #pragma unroll
        for (int c = 0; c < 8; ++c)
            g_h[(size_t)row*DIM + tx*8 + c] = acc[a][c] + g_gb[(row/GS)*DIM + tx*8 + c];
    }
}

// ---- fused GEMM: hQ = h@WQr, hK = h@WKr (shared A tile) ----
__global__ __launch_bounds__(256) void k_gemmQK(const float* __restrict__ BQ, const float* __restrict__ BK){
    __shared__ float As[64][17];
    __shared__ float BsQ[16][128];
    __shared__ float BsK[16][128];
    const float* A = g_h;
    int tid = threadIdx.x;
    int tx = tid & 15, ty = tid >> 4;
    int row0 = blockIdx.x * 64;
    float accQ[4][8], accK[4][8];
    #pragma unroll
    for (int a = 0; a < 4; ++a)
        #pragma unroll
        for (int c = 0; c < 8; ++c){ accQ[a][c] = 0.f; accK[a][c] = 0.f; }
    int la_r = tid >> 2, la_k = (tid & 3)*4;
    int lb_r = tid >> 4, lb_c = (tid & 15)*8;
    for (int kc = 0; kc < DIM; kc += 16){
        float4 av = *reinterpret_cast<const float4*>(A + (size_t)(row0+la_r)*DIM + kc + la_k);
        size_t boff = (size_t)(lb_c>>5)*4096 + (kc+lb_r)*32 + (lb_c&31);
        float4 bq0 = *reinterpret_cast<const float4*>(BQ + boff);
        float4 bq1 = *reinterpret_cast<const float4*>(BQ + boff + 4);
        float4 bk0 = *reinterpret_cast<const float4*>(BK + boff);
        float4 bk1 = *reinterpret_cast<const float4*>(BK + boff + 4);
        As[la_r][la_k+0]=av.x; As[la_r][la_k+1]=av.y; As[la_r][la_k+2]=av.z; As[la_r][la_k+3]=av.w;
        *reinterpret_cast<float4*>(&BsQ[lb_r][lb_c])   = bq0;
        *reinterpret_cast<float4*>(&BsQ[lb_r][lb_c+4]) = bq1;
        *reinterpret_cast<float4*>(&BsK[lb_r][lb_c])   = bk0;
        *reinterpret_cast<float4*>(&BsK[lb_r][lb_c+4]) = bk1;
        __syncthreads();
        #pragma unroll
        for (int k = 0; k < 16; ++k){
            float a0=As[ty*4+0][k], a1=As[ty*4+1][k], a2=As[ty*4+2][k], a3=As[ty*4+3][k];
            float4 q0 = *reinterpret_cast<const float4*>(&BsQ[k][tx*8]);
            float4 q1 = *reinterpret_cast<const float4*>(&BsQ[k][tx*8+4]);
            float4 k0 = *reinterpret_cast<const float4*>(&BsK[k][tx*8]);
            float4 k1 = *reinterpret_cast<const float4*>(&BsK[k][tx*8+4]);
            float bq[8] = {q0.x,q0.y,q0.z,q0.w,q1.x,q1.y,q1.z,q1.w};
            float bk[8] = {k0.x,k0.y,k0.z,k0.w,k1.x,k1.y,k1.z,k1.w};
            #pragma unroll
            for (int c = 0; c < 8; ++c){
                accQ[0][c]=fmaf(a0,bq[c],accQ[0][c]); accQ[1][c]=fmaf(a1,bq[c],accQ[1][c]);
                accQ[2][c]=fmaf(a2,bq[c],accQ[2][c]); accQ[3][c]=fmaf(a3,bq[c],accQ[3][c]);
                accK[0][c]=fmaf(a0,bk[c],accK[0][c]); accK[1][c]=fmaf(a1,bk[c],accK[1][c]);
                accK[2][c]=fmaf(a2,bk[c],accK[2][c]); accK[3][c]=fmaf(a3,bk[c],accK[3][c]);
            }
        }
        __syncthreads();
    }
    #pragma unroll
    for (int a = 0; a < 4; ++a){
        int row = row0 + ty*4 + a;
        #pragma unroll
        for (int c = 0; c < 8; ++c){
            g_hQ[(size_t)row*DIM + tx*8 + c] = accQ[a][c];
            g_hK[(size_t)row*DIM + tx*8 + c] = accK[a][c];
        }
    }
}

// ---- qW via precomputed Mt: qW[b,combo,h][t] = sum_k x_sel[k] * Mt[mat][k][t] ----
__global__ __launch_bounds__(256) void k_qW2(const int* __restrict__ fixed_action){
    __shared__ float xs[8][128];
    int combo = blockIdx.x, b0 = blockIdx.y * 8;
    int tid = threadIdx.x, t = tid & 127, hp = tid >> 7;
    for (int idx = tid; idx < 8*128; idx += 256){
        int r = idx >> 7, c = idx & 127;
        int pos = 1 + fixed_action[(b0+r)*3];
        int sel = (combo & 2) ? pos + HALF : pos;
        xs[r][c] = g_h[((size_t)(b0+r)*GS + sel)*DIM + c];
    }
    __syncthreads();
    const float* Mbase = g_Mt + (size_t)(combo & 1)*4*DIM*DIM;
    for (int hh = hp; hh < 4; hh += 2){
        const float* Mh = Mbase + (size_t)hh*DIM*DIM;
        float acc[8];
        #pragma unroll
        for (int r = 0; r < 8; ++r) acc[r] = 0.f;
        #pragma unroll 4
        for (int k = 0; k < DIM; ++k){
            float w = Mh[k*DIM + t];
            #pragma unroll
            for (int r = 0; r < 8; ++r) acc[r] = fmaf(xs[r][k], w, acc[r]);
        }
        #pragma unroll
        for (int r = 0; r < 8; ++r)
            g_qW[(((b0+r)*4 + combo)*4 + hh)*DIM + t] = acc[r];
    }
}

// ---- per-node layer-1 pre-activations ----
__global__ void k_uv(const int* __restrict__ rec, const float* __restrict__ i_w1,
                     const float* __restrict__ i_b1){
    int g = blockIdx.x, b = blockIdx.y, t = threadIdx.x;
    __shared__ float xg[DIM], xn[DIM], s[16];
    int rg = rec[b*GS + g];
    xg[t] = g_h[((size_t)b*GS + g )*DIM + t];
    xn[t] = g_h[((size_t)b*GS + rg)*DIM + t];
    __syncthreads();
    int d = t >> 3, l8 = t & 7;
    int combo = d >> 2, head = d & 3;
    const float* q = g_qW + ((b*4+combo)*4+head)*DIM;
    const float* x = (combo & 1) ? xn : xg;
    float p = 0.f;
    #pragma unroll
    for (int e = l8; e < DIM; e += 8) p = fmaf(q[e], x[e], p);
    p += __shfl_xor_sync(0xffffffffu, p, 4);
    p += __shfl_xor_sync(0xffffffffu, p, 2);
    p += __shfl_xor_sync(0xffffffffu, p, 1);
    if (l8 == 0) s[d] = p * NORMF;
    __syncthreads();
    if (t < 32){
        float u = i_b1[t];
        #pragma unroll
        for (int f = 0; f < 8; ++f) u = fmaf(s[f], i_w1[f*32+t], u);
        g_u[((size_t)b*GS + g)*32 + t] = u;
    } else if (t < 64){
        int c = t - 32;
        float v = 0.f;
        #pragma unroll
        for (int f = 0; f < 8; ++f) v = fmaf(s[8+f], i_w1[(8+f)*32+c], v);
        g_v[((size_t)b*GS + g)*32 + c] = v;
    }
}

// ---- removal scores ----
__global__ void k_removal(const int* __restrict__ rec, const float* __restrict__ sig,
                          const float* __restrict__ w1, const float* __restrict__ b1,
                          const float* __restrict__ w2, const float* __restrict__ b2,
                          const float* __restrict__ w3, const float* __restrict__ b3,
                          float* __restrict__ out){
    int b = blockIdx.x, t = threadIdx.x;
    __shared__ int rec_s[GS], pre_s[GS];
    __shared__ float red[4];
    __shared__ float tot_s;
    for (int g = t; g < GS; g += 128) rec_s[g] = rec[b*GS+g];
    __syncthreads();
    for (int g = t; g < GS; g += 128) pre_s[rec_s[g]] = g;
    __syncthreads();
    float e = 0.f;
    if (t < HALF){
        float feat[12];
        #pragma unroll
        for (int hf = 0; hf < 2; ++hf){
            int g = 1 + hf*HALF + t;
            int pg = pre_s[g];
            int og = rec_s[rec_s[g]];
            const float* Qg = g_hQ + ((size_t)b*GS + g )*DIM;
            const float* Kg = g_hK + ((size_t)b*GS + g )*DIM;
            const float* Qp = g_hQ + ((size_t)b*GS + pg)*DIM;
            const float* Kp = g_hK + ((size_t)b*GS + og)*DIM;
            #pragma unroll
            for (int h = 0; h < 4; ++h){
                float c1=0.f, c2=0.f, c3=0.f;
                #pragma unroll
                for (int k = 0; k < 32; ++k){
                    float qp=Qp[h*32+k], kg=Kg[h*32+k], qg=Qg[h*32+k], kp=Kp[h*32+k];
                    c1 = fmaf(qp, kg, c1);
                    c2 = fmaf(qg, kp, c2);
                    c3 = fmaf(qp, kp, c3);
                }
                feat[hf*4+h] = c1 + c2 - c3;
            }
        }
        #pragma unroll
        for (int s4 = 0; s4 < 4; ++s4) feat[8+s4] = sig[b*4*HALF + s4*HALF + t];
        float x1[32];
        #pragma unroll
        for (int c = 0; c < 32; ++c){
            float a = b1[c];
            #pragma unroll
            for (int f = 0; f < 12; ++f) a = fmaf(feat[f], w1[f*32+c], a);
            x1[c] = fmaxf(a, 0.f);
        }
        float y = b3[0];
        #pragma unroll
        for (int o = 0; o < 32; ++o){
            float a = b2[o];
            #pragma unroll
            for (int k = 0; k < 32; ++k) a = fmaf(x1[k], w2[k*32+o], a);
            y = fmaf(fmaxf(a, 0.f), w3[o], y);
        }
        e = __expf(6.f * tanhf(y));
    }
    float w = e;
    #pragma unroll
    for (int o = 16; o; o >>= 1) w += __shfl_xor_sync(0xffffffffu, w, o);
    if ((t & 31) == 0) red[t>>5] = w;
    __syncthreads();
    if (t == 0) tot_s = red[0]+red[1]+red[2]+red[3];
    __syncthreads();
    if (t < HALF) out[(size_t)b*OUTS + t] = e / tot_s;
}

// ---- table MLP v3: stream-k, 32 packed accs, LDS.128 weight loads ----
__global__ __launch_bounds__(256, 2) void k_table(
        const float* __restrict__ i_w2, const float* __restrict__ i_b2,
        const float* __restrict__ i_w3, const float* __restrict__ i_b3,
        const unsigned char* __restrict__ mask, float* __restrict__ out){
    __shared__ unsigned long long w2k[32][32];
    __shared__ float2 vp[32][101];
    __shared__ float us[8][32];
    __shared__ unsigned long long b2d[32];
    __shared__ float w3s[32];
    __shared__ float red[8];
    int tid = threadIdx.x, b = blockIdx.y, it = blockIdx.x;
    int lane = tid & 31, il = tid >> 5;

    for (int idx = tid; idx < 1024; idx += 256){
        int k = idx >> 5, o = idx & 31;
        float w = i_w2[k*32+o];
        w2k[k][o] = pack2(w, w);
    }
    if (tid < 32){
        float bb = i_b2[tid];
        b2d[tid] = pack2(bb, bb);
        w3s[tid] = i_w3[tid];
    }
    const float* vbase = g_v + (size_t)b*GS*32;
    for (int idx = tid; idx < 32*101; idx += 256){
        int k = idx / 101, jp = idx - 101*(idx/101);
        int j0 = 2*jp, j1 = min(2*jp+1, GS-1);
        vp[k][jp] = make_float2(vbase[(size_t)j0*32 + k], vbase[(size_t)j1*32 + k]);
    }
    {
        int i = it*8 + (tid >> 5);
        us[tid>>5][lane] = (i < GS) ? g_u[((size_t)b*GS + i)*32 + lane] : 0.f;
    }
    __syncthreads();

    int i = it*8 + il;
    bool iok = (i < GS);
    float b3v = i_b3[0];
    float lsum = 0.f;
    const unsigned char* mrow = mask + ((size_t)b*GS + i)*GS;
    float* orow = out + (size_t)b*OUTS + HALF + (size_t)i*GS;

    #pragma unroll 1
    for (int p = 0; p < 4; ++p){
        int jp = p*32 + lane;
        int jpc = min(jp, 100);
        unsigned long long acc[32];
        #pragma unroll
        for (int o = 0; o < 32; ++o) acc[o] = b2d[o];
        #pragma unroll 8
        for (int k = 0; k < 32; ++k){
            float2 v2 = vp[k][jpc];
            float uk = us[il][k];
            unsigned long long h = pack2(fmaxf(uk + v2.x, 0.f), fmaxf(uk + v2.y, 0.f));
            const ulonglong2* wrow = reinterpret_cast<const ulonglong2*>(&w2k[k][0]);
            #pragma unroll
            for (int o2 = 0; o2 < 16; ++o2){
                ulonglong2 ww = wrow[o2];
                acc[2*o2]   = fma2(h, ww.x, acc[2*o2]);
                acc[2*o2+1] = fma2(h, ww.y, acc[2*o2+1]);
            }
        }
        float y0 = b3v, y1 = b3v;
        #pragma unroll
        for (int o = 0; o < 32; ++o){
            float2 r = unpack2(acc[o]);
            y0 = fmaf(fmaxf(r.x, 0.f), w3s[o], y0);
            y1 = fmaf(fmaxf(r.y, 0.f), w3s[o], y1);
        }
        int j0 = 2*jp, j1 = j0 + 1;
        if (iok && j0 < GS){
            float e = mrow[j0] ? 0.f : __expf(6.f * fast_tanh(y0));
            orow[j0] = e; lsum += e;
            if (j1 < GS){
                float e1 = mrow[j1] ? 0.f : __expf(6.f * fast_tanh(y1));
                orow[j1] = e1; lsum += e1;
            }
        }
    }
    #pragma unroll
    for (int o = 16; o; o >>= 1) lsum += __shfl_xor_sync(0xffffffffu, lsum, o);
    if (lane == 0) red[il] = lsum;
    __syncthreads();
    if (tid == 0){
        float tot = 0.f;
        #pragma unroll
        for (int w = 0; w < 8; ++w) tot += red[w];
        g_part[b*NTILES + it] = tot;
    }
}

// ---- deterministic row sums -> reciprocal ----
__global__ void k_inv(){
    int b = blockIdx.x, t = threadIdx.x;
    float v = (t < NTILES) ? g_part[b*NTILES + t] : 0.f;
    #pragma unroll
    for (int o = 16; o; o >>= 1) v += __shfl_xor_sync(0xffffffffu, v, o);
    if (t == 0) g_sums[b] = __frcp_rn(v);
}

// ---- normalize reinsertion block ----
__global__ void k_scale(float* __restrict__ out){
    int idx = blockIdx.x*256 + threadIdx.x;
    if (idx >= BS*GS2) return;
    int b = idx / GS2;
    out[(size_t)b*OUTS + HALF + (idx - b*GS2)] *= g_sums[b];
}

extern "C" void kernel_launch(void* const* d_in, const int* in_sizes, int n_in,
                              void* d_out, int out_size) {
    const float* h_em  = (const float*)d_in[0];
    const float* sig   = (const float*)d_in[1];
    const float* Wn    = (const float*)d_in[2];
    const float* Wg    = (const float*)d_in[3];
    const float* WQr   = (const float*)d_in[4];
    const float* WKr   = (const float*)d_in[5];
    const float* r_w1  = (const float*)d_in[6];
    const float* r_b1  = (const float*)d_in[7];
    const float* r_w2  = (const float*)d_in[8];
    const float* r_b2  = (const float*)d_in[9];
    const float* r_w3  = (const float*)d_in[10];
    const float* r_b3  = (const float*)d_in[11];
    const float* Wq1   = (const float*)d_in[12];
    const float* Wk1   = (const float*)d_in[13];
    const float* Wq2   = (const float*)d_in[14];
    const float* Wk2   = (const float*)d_in[15];
    const float* i_w1  = (const float*)d_in[16];
    const float* i_b1  = (const float*)d_in[17];
    const float* i_w2  = (const float*)d_in[18];
    const float* i_b2  = (const float*)d_in[19];
    const float* i_w3  = (const float*)d_in[20];
    const float* i_b3  = (const float*)d_in[21];
    const int*   rec   = (const int*)d_in[22];
    const int*   fixed = (const int*)d_in[23];
    const unsigned char* mask = (const unsigned char*)d_in[24];
    float* out = (float*)d_out;

    k_prep<<<dim3(8, 8), 256>>>(Wq1, Wk1, Wq2, Wk2);   // #1
    k_gg<<<BS, 128>>>(h_em, Wg);                       // #2
    k_gemm0<<<402, 256>>>(h_em, Wn);                   // #3
    k_qW2<<<dim3(4, 16), 256>>>(fixed);                // #4  (ncu capture slot)
    k_uv<<<dim3(GS, BS), 128>>>(rec, i_w1, i_b1);      // #5
    k_table<<<dim3(NTILES, BS), 256>>>(i_w2, i_b2, i_w3, i_b3, mask, out);  // #6
    k_gemmQK<<<402, 256>>>(WQr, WKr);                  // #7
    k_removal<<<BS, 128>>>(rec, sig, r_w1, r_b1, r_w2, r_b2, r_w3, r_b3, out);
    k_inv<<<BS, 32>>>();
    k_scale<<<(BS*GS2 + 255)/256, 256>>>(out);
}